// round 16
// baseline (speedup 1.0000x reference)
#include <cuda_runtime.h>
#include <cstdint>

// Motion loss on GB300: PERSISTENT software-pipelined blocks. Grid = 296
// (2 blocks/SM, one wave), 128 threads, double-buffered 64-row tiles
// (2 x 50.7 KB). While computing tile t from buf k, each thread stages tile
// t+296 into buf k^1 in 3 LDG->STS chunks interleaved between jstep groups,
// so DRAM streams during compute instead of alternating with it (R3's
// profile showed pipelined warps sustain chain-limited issue ~0.275/cyc ->
// 8 warps/SM suffice once loads overlap). Compute = R14's warp-specialized
// packed-f32x2 FK, unchanged.

namespace {

constexpr int ROW   = 99;                  // floats per row (per array)
constexpr int TROWS = 64;                  // rows per tile
constexpr int TPB   = 128;                 // 2 threads per row
constexpr int NBT   = 64 * 2048;           // 131072 rows
constexpr int NT    = NBT / TROWS;         // 2048 tiles
constexpr int GRID  = 296;                 // persistent blocks (2/SM x 148)
constexpr int TILE_F4 = TROWS * ROW / 4;   // 1584 float4 per array per tile

constexpr int BUF_U64   = TROWS * ROW;     // 6336 u64 pairs per buffer
constexpr int BONES_OFF = 2 * BUF_U64;     // u64 units: bones buf0/buf1 (72 each)
constexpr int G9_OFF    = BONES_OFF + 2 * 72;
constexpr int SMEM_U64  = G9_OFF + TROWS * 7 + 8;
constexpr int SMEM_BYTES = SMEM_U64 * 8;   // ~106.2 KB -> 2 blocks/SM

// joint terms owned by exactly one thread -> full weight
constexpr float S1 = 1.0f / (float(NBT) * 96.0f);
constexpr float S2 = 2.5f / (float(NBT) * 72.0f);
// root terms computed by both threads of a row -> half weight
constexpr float S1h  = 0.5f * S1;
constexpr float S23h = 0.5f * (S2 + 1.0f / (float(NBT) * 3.0f));

} // namespace

__device__ float    g_partials[GRID];
__device__ unsigned g_count = 0;

using u32 = unsigned int;
using u64 = unsigned long long;

// ---- packed f32x2 primitives ----
__device__ __forceinline__ u64 pk2(float lo, float hi) {
    u64 r;
    asm("mov.b64 %0, {%1, %2};" : "=l"(r)
        : "r"(__float_as_uint(lo)), "r"(__float_as_uint(hi)));
    return r;
}
__device__ __forceinline__ void upk2(u64 v, float& lo, float& hi) {
    u32 a, b;
    asm("mov.b64 {%0, %1}, %2;" : "=r"(a), "=r"(b) : "l"(v));
    lo = __uint_as_float(a); hi = __uint_as_float(b);
}
__device__ __forceinline__ u64 fm2(u64 a, u64 b, u64 c) {
    u64 r; asm("fma.rn.f32x2 %0, %1, %2, %3;" : "=l"(r) : "l"(a), "l"(b), "l"(c));
    return r;
}
__device__ __forceinline__ u64 ml2(u64 a, u64 b) {
    u64 r; asm("mul.rn.f32x2 %0, %1, %2;" : "=l"(r) : "l"(a), "l"(b));
    return r;
}
__device__ __forceinline__ u64 ad2(u64 a, u64 b) {
    u64 r; asm("add.rn.f32x2 %0, %1, %2;" : "=l"(r) : "l"(a), "l"(b));
    return r;
}

constexpr u64 NEG1 = 0xBF800000BF800000ULL;
constexpr u64 TWO  = 0x4000000040000000ULL;

struct PXf { u64 qw, qx, qy, qz, tx, ty, tz; };

// (hi-lo)^2 accumulate
__device__ __forceinline__ void d2(u64 v, float& s) {
    float a, b; upk2(v, a, b);
    float d = a - b;
    s = fmaf(d, d, s);
}

__device__ __forceinline__ void pcompose(const PXf& p,
                                         u64 lw, u64 lx, u64 ly, u64 lz,
                                         u64 bx, u64 by, u64 bz, PXf& o) {
    u64 nx = ml2(p.qx, NEG1), ny = ml2(p.qy, NEG1), nz = ml2(p.qz, NEG1);
    u64 cx = fm2(p.qy, bz, ml2(nz, by));
    u64 cy = fm2(p.qz, bx, ml2(nx, bz));
    u64 cz = fm2(p.qx, by, ml2(ny, bx));
    u64 sx = fm2(p.qw, cx, fm2(p.qy, cz, ml2(nz, cy)));
    u64 sy = fm2(p.qw, cy, fm2(p.qz, cx, ml2(nx, cz)));
    u64 sz = fm2(p.qw, cz, fm2(p.qx, cy, ml2(ny, cx)));
    o.tx = fm2(TWO, sx, ad2(bx, p.tx));
    o.ty = fm2(TWO, sy, ad2(by, p.ty));
    o.tz = fm2(TWO, sz, ad2(bz, p.tz));
    u64 rw = fm2(p.qw, lw, fm2(nx, lx, fm2(ny, ly, ml2(nz, lz))));
    u64 rx = fm2(p.qw, lx, fm2(lw, p.qx, fm2(p.qy, lz, ml2(nz, ly))));
    u64 ry = fm2(p.qw, ly, fm2(lw, p.qy, fm2(p.qz, lx, ml2(nx, lz))));
    u64 rz = fm2(p.qw, lz, fm2(lw, p.qz, fm2(p.qx, ly, ml2(ny, lx))));
    o.qw = rw; o.qx = rx; o.qy = ry; o.qz = rz;
}

// one non-root joint (both skeletons); j is compile-time constant at call site
__device__ __forceinline__ void jstep(const u64* __restrict__ r,
                                      const u64* __restrict__ bn,
                                      int j, const PXf& P, PXf& O, float& acc) {
    u64 w = r[4*j+0], x = r[4*j+1], y = r[4*j+2], z = r[4*j+3];

    u64 n2 = ml2(w, w); n2 = fm2(x, x, n2); n2 = fm2(y, y, n2); n2 = fm2(z, z, n2);
    float na, nb; upk2(n2, na, nb);
    u64 inv = pk2(rsqrtf(na), rsqrtf(nb));
    w = ml2(w, inv); x = ml2(x, inv); y = ml2(y, inv); z = ml2(z, inv);

    float s = 0.f;
    d2(w, s); d2(x, s); d2(y, s); d2(z, s);
    acc = fmaf(S1, s, acc);

    pcompose(P, w, x, y, z, bn[3*j+0], bn[3*j+1], bn[3*j+2], O);

    float t = 0.f;
    d2(O.tx, t); d2(O.ty, t); d2(O.tz, t);
    acc = fmaf(S2, t, acc);
}

// ---- staging chunks: last absolute index (12) is the only guarded one ----
template<int K0, int N>
__device__ __forceinline__ void ldg_chunk(const float4* __restrict__ gx,
                                          const float4* __restrict__ gy,
                                          int tid, float4* ra, float4* rc) {
#pragma unroll
    for (int kk = 0; kk < N; ++kk) {
        int i = tid + (K0 + kk) * TPB;
        if (K0 + kk < 12 || tid < TILE_F4 - 12 * TPB) {
            ra[kk] = __ldg(gx + i);
            rc[kk] = __ldg(gy + i);
        }
    }
}
template<int K0, int N>
__device__ __forceinline__ void sts_chunk(float4* __restrict__ d, int tid,
                                          const float4* ra, const float4* rc) {
#pragma unroll
    for (int kk = 0; kk < N; ++kk) {
        int i = tid + (K0 + kk) * TPB;
        if (K0 + kk < 12 || tid < TILE_F4 - 12 * TPB) {
            d[2*i + 0] = make_float4(ra[kk].x, rc[kk].x, ra[kk].y, rc[kk].y);
            d[2*i + 1] = make_float4(ra[kk].z, rc[kk].z, ra[kk].w, rc[kk].w);
        }
    }
}

__global__ __launch_bounds__(TPB, 2)
void motion_loss_kernel(const float* __restrict__ Ym,
                        const float* __restrict__ Xm,
                        const float* __restrict__ Yt,
                        const float* __restrict__ Xt,
                        float* __restrict__ out)
{
    extern __shared__ float smf[];
    u64* smu = (u64*)smf;
    const int tid = threadIdx.x;
    const int bid = blockIdx.x;

    const int lane = tid & 31;
    const int wid  = tid >> 5;                 // 0..3
    const int isB  = wid & 1;                  // even warp = half A, odd = half B
    const int row  = (wid >> 1) * 32 + lane;   // row within tile (0..63)
    const unsigned FULL = 0xffffffffu;

    float acc = 0.f;

    // ---- prologue: stage tile `bid` into buffer 0 ----
    {
        const float4* gx = (const float4*)(Xm + (size_t)bid * TROWS * ROW);
        const float4* gy = (const float4*)(Ym + (size_t)bid * TROWS * ROW);
        float4* d = (float4*)smu;
#pragma unroll
        for (int kk = 0; kk < 13; ++kk) {
            int i = tid + kk * TPB;
            if (kk < 12 || tid < TILE_F4 - 12 * TPB) {
                float4 a = __ldg(gx + i);
                float4 c = __ldg(gy + i);
                d[2*i + 0] = make_float4(a.x, c.x, a.y, c.y);
                d[2*i + 1] = make_float4(a.z, c.z, a.w, c.w);
            }
        }
        const int b0 = bid >> 5;               // 32 tiles per batch item
        if (tid < 72) {
            float2* bt = (float2*)(smu + BONES_OFF);
            bt[tid] = make_float2(Xt[b0 * 72 + tid], Yt[b0 * 72 + tid]);
        }
    }
    __syncthreads();

    // ---- persistent pipelined main loop ----
    int kb = 0;
    for (int t = bid; t < NT; t += GRID, kb ^= 1) {
        const bool pre = (t + GRID) < NT;

        const u64* r  = smu + (size_t)kb * BUF_U64 + (size_t)row * ROW;
        const u64* bn = smu + BONES_OFF + kb * 72;
        u64* g9s      = smu + G9_OFF + (size_t)row * 7;

        const float4* gx = (const float4*)(Xm + (size_t)(t + GRID) * TROWS * ROW);
        const float4* gy = (const float4*)(Ym + (size_t)(t + GRID) * TROWS * ROW);
        float4*  dN  = (float4*)(smu + (size_t)(kb ^ 1) * BUF_U64);
        float2*  btN = (float2*)(smu + BONES_OFF + (kb ^ 1) * 72);
        const int bnext = (t + GRID) >> 5;

        float4 ra[5], rc[5];
        float bna = 0.f, bnc = 0.f;

        if (pre) {
            ldg_chunk<0, 4>(gx, gy, tid, ra, rc);
            if (tid < 72) { bna = Xt[bnext * 72 + tid]; bnc = Yt[bnext * 72 + tid]; }
        }

        // ---- root (both warps of a pair; half weights) ----
        PXf P0;
        {
            u64 w = r[0], x = r[1], y = r[2], z = r[3];
            u64 n2 = ml2(w, w); n2 = fm2(x, x, n2); n2 = fm2(y, y, n2); n2 = fm2(z, z, n2);
            float na, nb; upk2(n2, na, nb);
            u64 inv = pk2(rsqrtf(na), rsqrtf(nb));
            w = ml2(w, inv); x = ml2(x, inv); y = ml2(y, inv); z = ml2(z, inv);

            float s = 0.f;
            d2(w, s); d2(x, s); d2(y, s); d2(z, s);
            acc = fmaf(S1h, s, acc);

            P0.qw = w; P0.qx = x; P0.qy = y; P0.qz = z;
            P0.tx = r[96]; P0.ty = r[97]; P0.tz = r[98];
            float tt = 0.f;
            d2(P0.tx, tt); d2(P0.ty, tt); d2(P0.tz, tt);
            acc = fmaf(S23h, tt, acc);
        }

        // ---- phase 1 ----
        PXf G9v;
        if (!isB) {
            jstep(r, bn, 3, P0, G9v, acc);
            jstep(r, bn, 6, G9v, G9v, acc);
            jstep(r, bn, 9, G9v, G9v, acc);
            g9s[0] = G9v.qw; g9s[1] = G9v.qx; g9s[2] = G9v.qy; g9s[3] = G9v.qz;
            g9s[4] = G9v.tx; g9s[5] = G9v.ty; g9s[6] = G9v.tz;
        } else {
            PXf C;
            jstep(r, bn,  2, P0, C, acc);
            jstep(r, bn,  5, C,  C, acc);
            jstep(r, bn,  8, C,  C, acc);
            jstep(r, bn, 11, C,  C, acc);
        }

        if (pre) {
            sts_chunk<0, 4>(dN, tid, ra, rc);
            ldg_chunk<4, 5>(gx, gy, tid, ra, rc);
        }
        __syncthreads();                       // publish G9 (staging unharmed)

        // ---- phase 2, part 1 ----
        PXf C1, C2;
        if (!isB) {
            jstep(r, bn,  1, P0,  C1, acc);
            jstep(r, bn, 13, G9v, C2, acc);
            jstep(r, bn,  4, C1,  C1, acc);
            jstep(r, bn, 16, C2,  C2, acc);
        } else {
            PXf P9;
            P9.qw = g9s[0]; P9.qx = g9s[1]; P9.qy = g9s[2]; P9.qz = g9s[3];
            P9.tx = g9s[4]; P9.ty = g9s[5]; P9.tz = g9s[6];
            jstep(r, bn, 12, P9, C1, acc);
            jstep(r, bn, 14, P9, C2, acc);
            jstep(r, bn, 15, C1, C1, acc);
            jstep(r, bn, 17, C2, C2, acc);
        }

        if (pre) {
            sts_chunk<4, 5>(dN, tid, ra, rc);
            ldg_chunk<9, 4>(gx, gy, tid, ra, rc);
            if (tid < 72) btN[tid] = make_float2(bna, bnc);
        }

        // ---- phase 2, part 2 ----
        if (!isB) {
            jstep(r, bn,  7, C1, C1, acc);
            jstep(r, bn, 18, C2, C2, acc);
            jstep(r, bn, 10, C1, C1, acc);
            jstep(r, bn, 20, C2, C2, acc);
            jstep(r, bn, 22, C2, C2, acc);
        } else {
            jstep(r, bn, 19, C2, C2, acc);
            jstep(r, bn, 21, C2, C2, acc);
            jstep(r, bn, 23, C2, C2, acc);
        }

        if (pre) sts_chunk<9, 4>(dN, tid, ra, rc);
        __syncthreads();                       // next buffer staged; current reads done
    }

    // ---- block reduction (4 warps) ----
    #pragma unroll
    for (int o = 16; o > 0; o >>= 1) acc += __shfl_xor_sync(FULL, acc, o);

    __shared__ float wsum[4];
    __shared__ int   s_last;
    if (lane == 0) wsum[wid] = acc;
    __syncthreads();

    if (tid == 0) {
        g_partials[bid] = wsum[0] + wsum[1] + wsum[2] + wsum[3];
        __threadfence();
        unsigned ticket = atomicAdd(&g_count, 1u);
        s_last = (ticket == GRID - 1) ? 1 : 0;
    }
    __syncthreads();

    // ---- last block: deterministic fixed-order final sum of 296 partials ----
    if (s_last) {
        double v = 0.0;
        for (int i = tid; i < GRID; i += TPB) v += (double)g_partials[i];

        __shared__ double dsum[TPB];
        dsum[tid] = v;
        __syncthreads();
        #pragma unroll
        for (int o = TPB / 2; o > 0; o >>= 1) {
            if (tid < o) dsum[tid] += dsum[tid + o];
            __syncthreads();
        }
        if (tid == 0) {
            out[0] = (float)dsum[0];
            g_count = 0;                       // reset for next graph replay
        }
    }
}

extern "C" void kernel_launch(void* const* d_in, const int* in_sizes, int n_in,
                              void* d_out, int out_size)
{
    (void)in_sizes; (void)n_in; (void)out_size;
    const float* Ym = (const float*)d_in[0];
    const float* Xm = (const float*)d_in[1];
    const float* Yt = (const float*)d_in[2];
    const float* Xt = (const float*)d_in[3];

    cudaFuncSetAttribute(motion_loss_kernel,
                         cudaFuncAttributeMaxDynamicSharedMemorySize, SMEM_BYTES);
    motion_loss_kernel<<<GRID, TPB, SMEM_BYTES>>>(Ym, Xm, Yt, Xt, (float*)d_out);
}